// round 1
// baseline (speedup 1.0000x reference)
#include <cuda_runtime.h>

#define Bsz   16
#define CIN   512
#define COUT  512
#define SDIM  512
#define HWDIM 32
#define OG    16   // out channels per conv block
#define ICC   4    // input channels per shared-mem chunk

// scratch (no allocations allowed)
__device__ float g_s[Bsz * CIN];      // modulation scales s[b,i]
__device__ float g_d[Bsz * COUT];     // demod factors d[b,o]
__device__ float g_wsq[COUT * CIN];   // sum_k cw[o,i,k]^2

// ---------------------------------------------------------------------------
// s[b,i] = sum_j style[b,j] * aff_w[i,j] * (1/sqrt(512)) + aff_b[i] + 1
// grid(B), block(512)
// ---------------------------------------------------------------------------
__global__ void k_style(const float* __restrict__ style,
                        const float* __restrict__ aff_w,
                        const float* __restrict__ aff_b) {
    __shared__ float st[SDIM];
    const int b = blockIdx.x;
    const int i = threadIdx.x;
    st[i] = style[b * SDIM + i];
    __syncthreads();
    const float aff_scale = 0.04419417382415922f;  // 1/sqrt(512)
    const float* __restrict__ wrow = aff_w + (long)i * SDIM;
    float acc = 0.f;
#pragma unroll 8
    for (int j = 0; j < SDIM; j++) acc += wrow[j] * st[j];
    g_s[b * CIN + i] = acc * aff_scale + aff_b[i] + 1.0f;
}

// ---------------------------------------------------------------------------
// wsq[o,i] = sum over 3x3 of conv_weight^2
// grid(COUT*CIN/256), block(256)
// ---------------------------------------------------------------------------
__global__ void k_wsq(const float* __restrict__ cw) {
    const int idx = blockIdx.x * blockDim.x + threadIdx.x;  // = o*CIN + i
    const float* __restrict__ p = cw + (long)idx * 9;
    float s = 0.f;
#pragma unroll
    for (int k = 0; k < 9; k++) s += p[k] * p[k];
    g_wsq[idx] = s;
}

// ---------------------------------------------------------------------------
// d[b,o] = rsqrt( w_scale^2 * sum_i s[b,i]^2 * wsq[o,i] + 1e-8 )
// grid(B), block(512)
// ---------------------------------------------------------------------------
__global__ void k_demod() {
    __shared__ float s2[CIN];
    const int b = blockIdx.x;
    const int o = threadIdx.x;
    const float sv = g_s[b * CIN + o];   // CIN == COUT == 512 == blockDim
    s2[o] = sv * sv;
    __syncthreads();
    const float* __restrict__ wr = g_wsq + (long)o * CIN;
    float acc = 0.f;
#pragma unroll 8
    for (int i = 0; i < CIN; i++) acc += wr[i] * s2[i];
    const float w_scale2 = 1.0f / 4608.0f;  // (1/sqrt(512*9))^2
    g_d[b * COUT + o] = rsqrtf(acc * w_scale2 + 1e-8f);
}

// ---------------------------------------------------------------------------
// out[b,o,y,x] = w_scale * d[b,o] * sum_{i,ky,kx} cw[o,i,ky,kx] *
//                                   (s[b,i]*x[b,i,y+ky-1,x+kx-1])
// block = (b, 16 out channels, full 32x32 image); 256 threads, 2x2 px/thread
// grid(COUT/OG, B), block(256)
// ---------------------------------------------------------------------------
__global__ void __launch_bounds__(256, 2)
k_conv(const float* __restrict__ x,
       const float* __restrict__ cw,
       float* __restrict__ out) {
    __shared__ float xs[ICC][34 * 34];     // padded input tile, modulated
    __shared__ float ws[OG][ICC][9];       // weights for this (og, ic-chunk)

    const int b  = blockIdx.y;
    const int o0 = blockIdx.x * OG;
    const int tid = threadIdx.x;
    const int qx = tid & 15;
    const int qy = tid >> 4;
    const int px = qx * 2;                 // this thread's 2x2 quad origin
    const int py = qy * 2;

    float acc[OG * 4];
#pragma unroll
    for (int i = 0; i < OG * 4; i++) acc[i] = 0.f;

    for (int ic0 = 0; ic0 < CIN; ic0 += ICC) {
        __syncthreads();  // previous chunk's compute done before overwrite

        // ---- load modulated, zero-padded input tile: ICC * 34 * 34 ----
        for (int idx = tid; idx < ICC * 1156; idx += 256) {
            const int ic  = idx / 1156;
            const int rem = idx - ic * 1156;
            const int row = rem / 34;
            const int yy  = row - 1;
            const int xx  = rem - row * 34 - 1;
            float v = 0.f;
            if ((unsigned)yy < 32u && (unsigned)xx < 32u)
                v = x[(((long)b * CIN + ic0 + ic) * HWDIM + yy) * HWDIM + xx]
                    * g_s[b * CIN + ic0 + ic];
            xs[ic][rem] = v;
        }

        // ---- load weights: OG * ICC * 9 ----
        for (int idx = tid; idx < OG * ICC * 9; idx += 256) {
            const int o   = idx / (ICC * 9);
            const int rem = idx - o * (ICC * 9);
            const int ic  = rem / 9;
            const int k   = rem - ic * 9;
            ws[o][ic][k] = cw[(((long)(o0 + o)) * CIN + ic0 + ic) * 9 + k];
        }
        __syncthreads();

        // ---- compute ----
#pragma unroll
        for (int ic = 0; ic < ICC; ic++) {
            float xv[16];  // 4x4 patch covering this thread's 2x2 outputs
#pragma unroll
            for (int r = 0; r < 4; r++)
#pragma unroll
                for (int c = 0; c < 4; c++)
                    xv[r * 4 + c] = xs[ic][(py + r) * 34 + px + c];

#pragma unroll
            for (int o = 0; o < OG; o++) {
#pragma unroll
                for (int ky = 0; ky < 3; ky++) {
#pragma unroll
                    for (int kx = 0; kx < 3; kx++) {
                        const float wv = ws[o][ic][ky * 3 + kx];
                        acc[o * 4 + 0] += wv * xv[(ky + 0) * 4 + kx + 0];
                        acc[o * 4 + 1] += wv * xv[(ky + 0) * 4 + kx + 1];
                        acc[o * 4 + 2] += wv * xv[(ky + 1) * 4 + kx + 0];
                        acc[o * 4 + 3] += wv * xv[(ky + 1) * 4 + kx + 1];
                    }
                }
            }
        }
    }

    // ---- epilogue: scale by w_scale * d[b,o] ----
    const float w_scale = 0.014731391274719736f;  // 1/sqrt(4608)
#pragma unroll
    for (int o = 0; o < OG; o++) {
        const float dm = g_d[b * COUT + o0 + o] * w_scale;
        float* __restrict__ op =
            out + (((long)b * COUT + o0 + o) * HWDIM + py) * HWDIM + px;
        op[0]         = acc[o * 4 + 0] * dm;
        op[1]         = acc[o * 4 + 1] * dm;
        op[HWDIM]     = acc[o * 4 + 2] * dm;
        op[HWDIM + 1] = acc[o * 4 + 3] * dm;
    }
}

// ---------------------------------------------------------------------------
extern "C" void kernel_launch(void* const* d_in, const int* in_sizes, int n_in,
                              void* d_out, int out_size) {
    const float* x      = (const float*)d_in[0];  // [16,512,32,32]
    const float* style  = (const float*)d_in[1];  // [16,512]
    const float* aff_w  = (const float*)d_in[2];  // [512,512]
    const float* aff_b  = (const float*)d_in[3];  // [512]
    const float* cw     = (const float*)d_in[4];  // [512,512,3,3]
    float* out          = (float*)d_out;          // [16,512,32,32]

    k_style<<<Bsz, SDIM>>>(style, aff_w, aff_b);
    k_wsq<<<(COUT * CIN) / 256, 256>>>(cw);
    k_demod<<<Bsz, COUT>>>();
    k_conv<<<dim3(COUT / OG, Bsz), 256>>>(x, cw, out);
}

// round 3
// speedup vs baseline: 4.6822x; 4.6822x over previous
#include <cuda_runtime.h>
#include <cuda_fp16.h>
#include <cstdint>

#define Bsz   16
#define CIN   512
#define COUT  512
#define SDIM  512
#define HWDIM 32

// ---------------- scratch (__device__ globals; no allocations) --------------
__device__ float g_s[Bsz * CIN];            // modulation s[b,i]
__device__ float g_d[Bsz * COUT];           // demod d[b,o]
__device__ float g_wsq[COUT * CIN];         // sum_k cw^2
__device__ __align__(16) __half g_w16[9 * COUT * CIN];          // [kk][o][ic]
__device__ __align__(16) __half g_x16[Bsz * 34 * 34 * CIN];     // [b][yy][xx][ic], zero halo

// ---------------- PTX helpers (base ISA only; NO tcgen05) -------------------
__device__ __forceinline__ uint32_t smem_u32(const void* p) {
    uint32_t a;
    asm("{ .reg .u64 t; cvta.to.shared.u64 t, %1; cvt.u32.u64 %0, t; }"
        : "=r"(a) : "l"(p));
    return a;
}
__device__ __forceinline__ void cp16(uint32_t s, const void* g) {
    asm volatile("cp.async.cg.shared.global [%0], [%1], 16;" :: "r"(s), "l"(g));
}
#define CP_COMMIT() asm volatile("cp.async.commit_group;" ::: "memory")
#define CP_WAIT1()  asm volatile("cp.async.wait_group 1;" ::: "memory")
#define CP_WAIT0()  asm volatile("cp.async.wait_group 0;" ::: "memory")

__device__ __forceinline__ void ldsm_x4(uint32_t* r, uint32_t addr) {
    asm volatile("ldmatrix.sync.aligned.m8n8.x4.shared.b16 {%0,%1,%2,%3}, [%4];"
        : "=r"(r[0]), "=r"(r[1]), "=r"(r[2]), "=r"(r[3]) : "r"(addr));
}
__device__ __forceinline__ void mma16816(float* c, const uint32_t* a, const uint32_t* b) {
    asm volatile("mma.sync.aligned.m16n8k16.row.col.f32.f16.f16.f32 "
        "{%0,%1,%2,%3}, {%4,%5,%6,%7}, {%8,%9}, {%0,%1,%2,%3};"
        : "+f"(c[0]), "+f"(c[1]), "+f"(c[2]), "+f"(c[3])
        : "r"(a[0]), "r"(a[1]), "r"(a[2]), "r"(a[3]), "r"(b[0]), "r"(b[1]));
}

// ---------------------------------------------------------------------------
// s[b,i] = style @ (aff_w/sqrt(512))^T + bias + 1        grid(B), block(512)
// ---------------------------------------------------------------------------
__global__ void k_style(const float* __restrict__ style,
                        const float* __restrict__ aff_w,
                        const float* __restrict__ aff_b) {
    __shared__ float st[SDIM];
    const int b = blockIdx.x, i = threadIdx.x;
    st[i] = style[b * SDIM + i];
    __syncthreads();
    const float aff_scale = 0.04419417382415922f;  // 1/sqrt(512)
    const float* __restrict__ wrow = aff_w + (long)i * SDIM;
    float acc = 0.f;
#pragma unroll 8
    for (int j = 0; j < SDIM; j++) acc += wrow[j] * st[j];
    g_s[b * CIN + i] = acc * aff_scale + aff_b[i] + 1.0f;
}

// ---------------------------------------------------------------------------
// wsq[o,i] = sum_k cw^2                         grid(COUT*CIN/256), block(256)
// ---------------------------------------------------------------------------
__global__ void k_wsq(const float* __restrict__ cw) {
    const int idx = blockIdx.x * blockDim.x + threadIdx.x;
    const float* __restrict__ p = cw + (long)idx * 9;
    float s = 0.f;
#pragma unroll
    for (int k = 0; k < 9; k++) s += p[k] * p[k];
    g_wsq[idx] = s;
}

// ---------------------------------------------------------------------------
// d[b,o] = rsqrt(w_scale^2 * sum_i s^2*wsq + 1e-8)        grid(B), block(512)
// ---------------------------------------------------------------------------
__global__ void k_demod() {
    __shared__ float s2[CIN];
    const int b = blockIdx.x, o = threadIdx.x;
    const float sv = g_s[b * CIN + o];
    s2[o] = sv * sv;
    __syncthreads();
    const float* __restrict__ wr = g_wsq + (long)o * CIN;
    float acc = 0.f;
#pragma unroll 8
    for (int i = 0; i < CIN; i++) acc += wr[i] * s2[i];
    g_d[b * COUT + o] = rsqrtf(acc * (1.0f / 4608.0f) + 1e-8f);
}

// ---------------------------------------------------------------------------
// w16[kk][o][ic] = fp16(cw[o][ic][kk])          grid(COUT*CIN/256), block(256)
// ---------------------------------------------------------------------------
__global__ void k_prep_w(const float* __restrict__ cw) {
    const int idx = blockIdx.x * blockDim.x + threadIdx.x;  // o*512+ic
    const float* __restrict__ p = cw + (long)idx * 9;
#pragma unroll
    for (int kk = 0; kk < 9; kk++)
        g_w16[kk * (COUT * CIN) + idx] = __float2half(p[kk]);
}

// ---------------------------------------------------------------------------
// zero g_x16 (halo must be zero)                         grid(4624), block(256)
// ---------------------------------------------------------------------------
__global__ void k_zero_x16() {
    const int idx = blockIdx.x * blockDim.x + threadIdx.x;
    reinterpret_cast<float4*>(g_x16)[idx] = make_float4(0.f, 0.f, 0.f, 0.f);
}

// ---------------------------------------------------------------------------
// x16[b][y+1][x+1][ic] = fp16(s[b,ic] * x[b,ic,y,x])   grid(16,16), block(256)
// ---------------------------------------------------------------------------
__global__ void k_prep_x(const float* __restrict__ x) {
    __shared__ float t[32][33];
    const int b = blockIdx.x;
    const int ic0 = blockIdx.y * 32;
    const int tid = threadIdx.x;
    for (int y = 0; y < 32; y++) {
#pragma unroll
        for (int ii = 0; ii < 4; ii++) {
            const int ic = ii * 8 + (tid >> 5);
            const int xc = tid & 31;
            t[ic][xc] = x[(((long)b * CIN + ic0 + ic) * 32 + y) * 32 + xc]
                        * g_s[b * CIN + ic0 + ic];
        }
        __syncthreads();
#pragma unroll
        for (int ii = 0; ii < 4; ii++) {
            const int xc = ii * 8 + (tid >> 5);
            const int ic = tid & 31;
            g_x16[(((long)b * 34 + y + 1) * 34 + xc + 1) * CIN + ic0 + ic] =
                __float2half(t[ic][xc]);
        }
        __syncthreads();
    }
}

// ---------------------------------------------------------------------------
// Implicit-GEMM conv via warp MMA (HMMA m16n8k16, fp16 in / fp32 acc).
// CTA: [M=128 out-ch, N=128 px (4 rows)]. 8 warps (2M x 4N), warp tile 64x32.
// K: 144 chunks of 32 (9 taps x 16 ic-chunks), cp.async double-buffered.
// grid(4, 8, 16), block(256)
// ---------------------------------------------------------------------------
#define ASTRIDE 80        // padded row stride (64B data + 16B pad)
#define ABUF    10240     // 128 rows * 80B
#define BUFSZ   20480     // A + B per stage
#define NCHUNK  144

__global__ void __launch_bounds__(256, 2)
k_conv_mma(float* __restrict__ out) {
    __shared__ __align__(16) unsigned char sbuf[2 * BUFSZ];

    const int b  = blockIdx.z;
    const int o0 = blockIdx.x * 128;
    const int y0 = blockIdx.y * 4;
    const int tid  = threadIdx.x;
    const int lane = tid & 31;
    const int wid  = tid >> 5;
    const int wm   = wid >> 2;     // 0..1  (M)
    const int wn   = wid & 3;      // 0..3  (N: one output row each)

    const uint32_t sb = smem_u32(sbuf);

    // loader coords: thread handles rows r0 and r0+64, 16B segment 'seg'
    const int seg = tid & 3;
    const int r0  = tid >> 2;      // 0..63
    const long xoff0 = ((long)(b * 34 + y0 + (r0 >> 5)) * 34 + (r0 & 31)) * CIN;
    const long xoff1 = ((long)(b * 34 + y0 + ((r0 + 64) >> 5)) * 34 + ((r0 + 64) & 31)) * CIN;

    float acc[4][4][4];
#pragma unroll
    for (int i = 0; i < 4; i++)
#pragma unroll
        for (int j = 0; j < 4; j++)
#pragma unroll
            for (int k = 0; k < 4; k++) acc[i][j][k] = 0.f;

    auto prefetch = [&](int c, int bi) {
        const int kk  = c >> 4;
        const int ic0 = (c & 15) << 5;
        const int ky  = kk / 3;
        const int kx  = kk - ky * 3;
        const uint32_t sa = sb + bi * BUFSZ;
        const __half* __restrict__ wa =
            g_w16 + (long)kk * (COUT * CIN) + ic0 + seg * 8;
        cp16(sa + r0 * ASTRIDE + seg * 16,        wa + (long)(o0 + r0) * CIN);
        cp16(sa + (r0 + 64) * ASTRIDE + seg * 16, wa + (long)(o0 + r0 + 64) * CIN);
        const __half* __restrict__ xb =
            g_x16 + (long)(ky * 34 + kx) * CIN + ic0 + seg * 8;
        const uint32_t sB = sa + ABUF;
        cp16(sB + r0 * ASTRIDE + seg * 16,        xb + xoff0);
        cp16(sB + (r0 + 64) * ASTRIDE + seg * 16, xb + xoff1);
    };

    prefetch(0, 0);
    CP_COMMIT();

    for (int c = 0; c < NCHUNK; c++) {
        const int bi = c & 1;
        if (c + 1 < NCHUNK) {
            prefetch(c + 1, bi ^ 1);
            CP_COMMIT();
            CP_WAIT1();
        } else {
            CP_WAIT0();
        }
        __syncthreads();

        const uint32_t A = sb + bi * BUFSZ;
        const uint32_t B = A + ABUF;
#pragma unroll
        for (int kh = 0; kh < 2; kh++) {
            uint32_t af[4][4], bf[2][4];
#pragma unroll
            for (int mt = 0; mt < 4; mt++) {
                const uint32_t row = wm * 64 + mt * 16 + (lane & 15);
                ldsm_x4(af[mt], A + row * ASTRIDE + kh * 32 + (lane >> 4) * 16);
            }
#pragma unroll
            for (int g = 0; g < 2; g++) {
                const uint32_t n = wn * 32 + g * 16 + ((lane >> 4) << 3) + (lane & 7);
                ldsm_x4(bf[g], B + n * ASTRIDE + kh * 32 + ((lane >> 3) & 1) * 16);
            }
#pragma unroll
            for (int mt = 0; mt < 4; mt++)
#pragma unroll
                for (int nt = 0; nt < 4; nt++)
                    mma16816(acc[mt][nt], af[mt], bf[nt >> 1] + (nt & 1) * 2);
        }
        __syncthreads();
    }

    // ---- epilogue: demod scale, direct coalesced v2 stores ----
    const float wsc = 0.014731391274719736f;  // 1/sqrt(4608)
    const int y = y0 + wn;                     // this warp's output row
#pragma unroll
    for (int mt = 0; mt < 4; mt++) {
        const int r    = wm * 64 + mt * 16 + (lane >> 2);
        const int o_lo = o0 + r;
        const int o_hi = o_lo + 8;
        const float d0 = g_d[b * COUT + o_lo] * wsc;
        const float d1 = g_d[b * COUT + o_hi] * wsc;
#pragma unroll
        for (int nt = 0; nt < 4; nt++) {
            const int xcol = nt * 8 + (lane & 3) * 2;
            float2 v0 = make_float2(acc[mt][nt][0] * d0, acc[mt][nt][1] * d0);
            float2 v1 = make_float2(acc[mt][nt][2] * d1, acc[mt][nt][3] * d1);
            *reinterpret_cast<float2*>(
                &out[(((long)b * COUT + o_lo) * 32 + y) * 32 + xcol]) = v0;
            *reinterpret_cast<float2*>(
                &out[(((long)b * COUT + o_hi) * 32 + y) * 32 + xcol]) = v1;
        }
    }
}

// ---------------------------------------------------------------------------
extern "C" void kernel_launch(void* const* d_in, const int* in_sizes, int n_in,
                              void* d_out, int out_size) {
    const float* x      = (const float*)d_in[0];  // [16,512,32,32]
    const float* style  = (const float*)d_in[1];  // [16,512]
    const float* aff_w  = (const float*)d_in[2];  // [512,512]
    const float* aff_b  = (const float*)d_in[3];  // [512]
    const float* cw     = (const float*)d_in[4];  // [512,512,3,3]
    float* out          = (float*)d_out;          // [16,512,32,32]

    k_style<<<Bsz, SDIM>>>(style, aff_w, aff_b);
    k_wsq<<<(COUT * CIN) / 256, 256>>>(cw);
    k_demod<<<Bsz, COUT>>>();
    k_prep_w<<<(COUT * CIN) / 256, 256>>>(cw);
    k_zero_x16<<<(Bsz * 34 * 34 * CIN / 8) / 256, 256>>>();
    k_prep_x<<<dim3(Bsz, CIN / 32), 256>>>(x);
    k_conv_mma<<<dim3(COUT / 128, 8, Bsz), 256>>>(out);
}

// round 5
// speedup vs baseline: 5.0437x; 1.0772x over previous
#include <cuda_runtime.h>
#include <cuda_fp16.h>
#include <cstdint>

#define Bsz   16
#define CIN   512
#define COUT  512
#define SDIM  512
#define HWDIM 32

// ---------------- scratch (__device__ globals; no allocations) --------------
__device__ float g_s[Bsz * CIN];            // modulation s[b,i]
__device__ float g_d[Bsz * COUT];           // demod d[b,o]
__device__ float g_wsq[COUT * CIN];         // sum_k cw^2
__device__ __align__(16) __half g_w16[9 * COUT * CIN];          // [kk][o][ic]
__device__ __align__(16) __half g_x16[Bsz * 34 * 34 * CIN];     // [b][yy][xx][ic], zero halo

// ---------------- PTX helpers (base ISA only) --------------------------------
__device__ __forceinline__ uint32_t smem_u32(const void* p) {
    uint32_t a;
    asm("{ .reg .u64 t; cvta.to.shared.u64 t, %1; cvt.u32.u64 %0, t; }"
        : "=r"(a) : "l"(p));
    return a;
}
__device__ __forceinline__ void cp16(uint32_t s, const void* g) {
    asm volatile("cp.async.cg.shared.global [%0], [%1], 16;" :: "r"(s), "l"(g));
}
#define CP_COMMIT() asm volatile("cp.async.commit_group;" ::: "memory")
#define CP_WAIT0()  asm volatile("cp.async.wait_group 0;" ::: "memory")

__device__ __forceinline__ void ldsm_x4(uint32_t* r, uint32_t addr) {
    asm volatile("ldmatrix.sync.aligned.m8n8.x4.shared.b16 {%0,%1,%2,%3}, [%4];"
        : "=r"(r[0]), "=r"(r[1]), "=r"(r[2]), "=r"(r[3]) : "r"(addr));
}
__device__ __forceinline__ void mma16816(float* c, const uint32_t* a, const uint32_t* b) {
    asm volatile("mma.sync.aligned.m16n8k16.row.col.f32.f16.f16.f32 "
        "{%0,%1,%2,%3}, {%4,%5,%6,%7}, {%8,%9}, {%0,%1,%2,%3};"
        : "+f"(c[0]), "+f"(c[1]), "+f"(c[2]), "+f"(c[3])
        : "r"(a[0]), "r"(a[1]), "r"(a[2]), "r"(a[3]), "r"(b[0]), "r"(b[1]));
}

// ---------------------------------------------------------------------------
// s[b,i] = style @ (aff_w/sqrt(512))^T + bias + 1        grid(B), block(512)
// ---------------------------------------------------------------------------
__global__ void k_style(const float* __restrict__ style,
                        const float* __restrict__ aff_w,
                        const float* __restrict__ aff_b) {
    __shared__ float st[SDIM];
    const int b = blockIdx.x, i = threadIdx.x;
    st[i] = style[b * SDIM + i];
    __syncthreads();
    const float aff_scale = 0.04419417382415922f;  // 1/sqrt(512)
    const float* __restrict__ wrow = aff_w + (long)i * SDIM;
    float acc = 0.f;
#pragma unroll 8
    for (int j = 0; j < SDIM; j++) acc += wrow[j] * st[j];
    g_s[b * CIN + i] = acc * aff_scale + aff_b[i] + 1.0f;
}

// ---------------------------------------------------------------------------
// fused: w16[kk][o][ic] = fp16(cw[o][ic][kk]);  wsq[o,i] = sum_k cw^2
// grid(COUT*CIN/256), block(256)
// ---------------------------------------------------------------------------
__global__ void k_prep_w(const float* __restrict__ cw) {
    const int idx = blockIdx.x * blockDim.x + threadIdx.x;  // o*512+ic
    const float* __restrict__ p = cw + (long)idx * 9;
    float v[9];
    float s = 0.f;
#pragma unroll
    for (int k = 0; k < 9; k++) { v[k] = p[k]; s += v[k] * v[k]; }
    g_wsq[idx] = s;
#pragma unroll
    for (int kk = 0; kk < 9; kk++)
        g_w16[kk * (COUT * CIN) + idx] = __float2half(v[kk]);
}

// ---------------------------------------------------------------------------
// d[b,o] = rsqrt(w_scale^2 * sum_i s^2*wsq + 1e-8)        grid(B), block(512)
// ---------------------------------------------------------------------------
__global__ void k_demod() {
    __shared__ float s2[CIN];
    const int b = blockIdx.x, o = threadIdx.x;
    const float sv = g_s[b * CIN + o];
    s2[o] = sv * sv;
    __syncthreads();
    const float* __restrict__ wr = g_wsq + (long)o * CIN;
    float acc = 0.f;
#pragma unroll 8
    for (int i = 0; i < CIN; i++) acc += wr[i] * s2[i];
    g_d[b * COUT + o] = rsqrtf(acc * (1.0f / 4608.0f) + 1e-8f);
}

// ---------------------------------------------------------------------------
// zero g_x16 (halo must be zero)                         grid(4624), block(256)
// ---------------------------------------------------------------------------
__global__ void k_zero_x16() {
    const int idx = blockIdx.x * blockDim.x + threadIdx.x;
    reinterpret_cast<float4*>(g_x16)[idx] = make_float4(0.f, 0.f, 0.f, 0.f);
}

// ---------------------------------------------------------------------------
// x16[b][y+1][x+1][ic] = fp16(s[b,ic] * x[b,ic,y,x])   grid(16,16), block(256)
// 4 image rows per stage, conflict-free 133-stride tile
// ---------------------------------------------------------------------------
__global__ void k_prep_x(const float* __restrict__ x) {
    __shared__ float t[32][133];           // [ic][r*33+xc]
    __shared__ float sm[32];
    const int b = blockIdx.x;
    const int ic0 = blockIdx.y * 32;
    const int tid = threadIdx.x;
    if (tid < 32) sm[tid] = g_s[b * CIN + ic0 + tid];
    __syncthreads();

    for (int y0 = 0; y0 < 32; y0 += 4) {
#pragma unroll
        for (int i = 0; i < 16; i++) {
            const int idx = i * 256 + tid;          // 4096 elems
            const int ic = idx >> 7;
            const int p  = idx & 127;
            const int r  = p >> 5, xc = p & 31;
            t[ic][r * 33 + xc] =
                x[(((long)b * CIN + ic0 + ic) * 32 + y0 + r) * 32 + xc] * sm[ic];
        }
        __syncthreads();
#pragma unroll
        for (int i = 0; i < 8; i++) {
            const int idx = i * 256 + tid;          // 2048 half2
            const int p    = idx >> 4;
            const int pair = idx & 15;
            const int r = p >> 5, xc = p & 31;
            const int ic = pair * 2;
            __half2 h = __floats2half2_rn(t[ic][r * 33 + xc], t[ic + 1][r * 33 + xc]);
            *reinterpret_cast<__half2*>(
                g_x16 + (((long)b * 34 + y0 + r + 1) * 34 + xc + 1) * CIN + ic0 + ic) = h;
        }
        __syncthreads();
    }
}

// ---------------------------------------------------------------------------
// Implicit-GEMM conv via warp MMA (HMMA m16n8k16, fp16 in / fp32 acc).
// CTA: [M=128 out-ch, N=128 px (4 rows)]. 8 warps (2M x 4N), warp tile 64x32.
// K: 72 chunks of 64 (9 taps x 8 ic-chunks), cp.async double-buffered.
// Pipeline per iter: wait0 -> sync -> prefetch(c+1) -> compute(c).
//   RAW: wait before sync publishes all threads' copies of group c.
//   WAR: sync (after all compute(c-1)) precedes overwrite of buffer bi^1.
// grid(4, 8, 16), block(256), dyn smem 2 x 36,864 B
// ---------------------------------------------------------------------------
#define ASTRIDE 144       // 128B data + 16B pad (conflict-free LDSM: 4-bank shift)
#define ABUF    18432     // 128 rows * 144B
#define STAGESZ 36864     // A + B per stage
#define NCHUNK  72

extern __shared__ unsigned char sbuf_dyn[];

__global__ void __launch_bounds__(256, 2)
k_conv_mma(float* __restrict__ out) {
    const int b  = blockIdx.z;
    const int o0 = blockIdx.x * 128;
    const int y0 = blockIdx.y * 4;
    const int tid  = threadIdx.x;
    const int lane = tid & 31;
    const int wid  = tid >> 5;
    const int wm   = wid >> 2;     // 0..1  (M)
    const int wn   = wid & 3;      // 0..3  (N: one output row each)

    const uint32_t sb = smem_u32(sbuf_dyn);

    // loader coords: seg = 16B segment of a 128B row; r = base row (0..31)
    const int seg = tid & 7;
    const int r   = tid >> 3;

    float acc[4][4][4];
#pragma unroll
    for (int i = 0; i < 4; i++)
#pragma unroll
        for (int j = 0; j < 4; j++)
#pragma unroll
            for (int k = 0; k < 4; k++) acc[i][j][k] = 0.f;

    auto prefetch = [&](int c, int bi) {
        const int kk  = c >> 3;              // tap 0..8
        const int ic0 = (c & 7) << 6;        // 0,64,...,448
        const int ky  = kk / 3;
        const int kx  = kk - ky * 3;
        const uint32_t sa = sb + bi * STAGESZ;
        const uint32_t sB = sa + ABUF;
        const __half* __restrict__ wa =
            g_w16 + (long)kk * (COUT * CIN) + ic0 + seg * 8;
        const __half* __restrict__ xb =
            g_x16 + (((long)b * 34 + y0 + ky) * 34 + (r + kx)) * CIN + ic0 + seg * 8;
#pragma unroll
        for (int k4 = 0; k4 < 4; k4++) {
            const int row = r + k4 * 32;     // A row = out-ch; B row = pixel
            cp16(sa + row * ASTRIDE + seg * 16, wa + (long)(o0 + row) * CIN);
            cp16(sB + row * ASTRIDE + seg * 16, xb + (long)k4 * 34 * CIN);
        }
    };

    prefetch(0, 0);
    CP_COMMIT();

    for (int c = 0; c < NCHUNK; c++) {
        const int bi = c & 1;
        CP_WAIT0();                      // my copies of group c done
        __syncthreads();                 // publish all threads' copies; close compute(c-1)
        if (c + 1 < NCHUNK) {
            prefetch(c + 1, bi ^ 1);     // safe: bi^1 last read in compute(c-1)
            CP_COMMIT();
        }

        const uint32_t A = sb + bi * STAGESZ;
        const uint32_t B = A + ABUF;
#pragma unroll
        for (int kh = 0; kh < 4; kh++) {
            uint32_t af[4][4], bf[2][4];
#pragma unroll
            for (int mt = 0; mt < 4; mt++) {
                const uint32_t row = wm * 64 + mt * 16 + (lane & 15);
                ldsm_x4(af[mt], A + row * ASTRIDE + kh * 32 + (lane >> 4) * 16);
            }
#pragma unroll
            for (int g = 0; g < 2; g++) {
                const uint32_t n = wn * 32 + g * 16 + ((lane >> 4) << 3) + (lane & 7);
                ldsm_x4(bf[g], B + n * ASTRIDE + kh * 32 + ((lane >> 3) & 1) * 16);
            }
#pragma unroll
            for (int mt = 0; mt < 4; mt++)
#pragma unroll
                for (int nt = 0; nt < 4; nt++)
                    mma16816(acc[mt][nt], af[mt], bf[nt >> 1] + (nt & 1) * 2);
        }
    }

    // ---- epilogue: demod scale, direct coalesced v2 stores ----
    const float wsc = 0.014731391274719736f;  // 1/sqrt(4608)
    const int y = y0 + wn;                     // this warp's output row
#pragma unroll
    for (int mt = 0; mt < 4; mt++) {
        const int rr   = wm * 64 + mt * 16 + (lane >> 2);
        const int o_lo = o0 + rr;
        const int o_hi = o_lo + 8;
        const float d0 = g_d[b * COUT + o_lo] * wsc;
        const float d1 = g_d[b * COUT + o_hi] * wsc;
#pragma unroll
        for (int nt = 0; nt < 4; nt++) {
            const int xcol = nt * 8 + (lane & 3) * 2;
            float2 v0 = make_float2(acc[mt][nt][0] * d0, acc[mt][nt][1] * d0);
            float2 v1 = make_float2(acc[mt][nt][2] * d1, acc[mt][nt][3] * d1);
            *reinterpret_cast<float2*>(
                &out[(((long)b * COUT + o_lo) * 32 + y) * 32 + xcol]) = v0;
            *reinterpret_cast<float2*>(
                &out[(((long)b * COUT + o_hi) * 32 + y) * 32 + xcol]) = v1;
        }
    }
}

// ---------------------------------------------------------------------------
extern "C" void kernel_launch(void* const* d_in, const int* in_sizes, int n_in,
                              void* d_out, int out_size) {
    const float* x      = (const float*)d_in[0];  // [16,512,32,32]
    const float* style  = (const float*)d_in[1];  // [16,512]
    const float* aff_w  = (const float*)d_in[2];  // [512,512]
    const float* aff_b  = (const float*)d_in[3];  // [512]
    const float* cw     = (const float*)d_in[4];  // [512,512,3,3]
    float* out          = (float*)d_out;          // [16,512,32,32]

    // unconditional + idempotent (no static guards allowed)
    cudaFuncSetAttribute(k_conv_mma,
                         cudaFuncAttributeMaxDynamicSharedMemorySize,
                         2 * STAGESZ);

    k_style<<<Bsz, SDIM>>>(style, aff_w, aff_b);
    k_prep_w<<<(COUT * CIN) / 256, 256>>>(cw);
    k_demod<<<Bsz, COUT>>>();
    k_zero_x16<<<(Bsz * 34 * 34 * CIN / 8) / 256, 256>>>();
    k_prep_x<<<dim3(Bsz, CIN / 32), 256>>>(x);
    k_conv_mma<<<dim3(COUT / 128, 8, Bsz), 256, 2 * STAGESZ>>>(out);
}

// round 6
// speedup vs baseline: 5.1292x; 1.0169x over previous
#include <cuda_runtime.h>
#include <cuda_fp16.h>
#include <cstdint>

#define Bsz   16
#define CIN   512
#define COUT  512
#define SDIM  512
#define HWDIM 32

// ---------------- scratch (__device__ globals; no allocations) --------------
__device__ float g_s[Bsz * CIN];            // modulation s[b,i]
__device__ float g_d[Bsz * COUT];           // demod d[b,o]
__device__ float g_wsq[COUT * CIN];         // sum_k cw^2
__device__ __align__(16) __half g_w16[9 * COUT * CIN];          // [kk][o][ic]
__device__ __align__(16) __half g_x16[Bsz * 34 * 34 * CIN];     // [b][yy][xx][ic], zero halo

// ---------------- PTX helpers (base ISA only) --------------------------------
__device__ __forceinline__ uint32_t smem_u32(const void* p) {
    uint32_t a;
    asm("{ .reg .u64 t; cvta.to.shared.u64 t, %1; cvt.u32.u64 %0, t; }"
        : "=r"(a) : "l"(p));
    return a;
}
__device__ __forceinline__ void cp16(uint32_t s, const void* g) {
    asm volatile("cp.async.cg.shared.global [%0], [%1], 16;" :: "r"(s), "l"(g));
}
#define CP_COMMIT() asm volatile("cp.async.commit_group;" ::: "memory")
#define CP_WAIT1()  asm volatile("cp.async.wait_group 1;" ::: "memory")

__device__ __forceinline__ void ldsm_x4(uint32_t* r, uint32_t addr) {
    asm volatile("ldmatrix.sync.aligned.m8n8.x4.shared.b16 {%0,%1,%2,%3}, [%4];"
        : "=r"(r[0]), "=r"(r[1]), "=r"(r[2]), "=r"(r[3]) : "r"(addr));
}
__device__ __forceinline__ void mma16816(float* c, const uint32_t* a, const uint32_t* b) {
    asm volatile("mma.sync.aligned.m16n8k16.row.col.f32.f16.f16.f32 "
        "{%0,%1,%2,%3}, {%4,%5,%6,%7}, {%8,%9}, {%0,%1,%2,%3};"
        : "+f"(c[0]), "+f"(c[1]), "+f"(c[2]), "+f"(c[3])
        : "r"(a[0]), "r"(a[1]), "r"(a[2]), "r"(a[3]), "r"(b[0]), "r"(b[1]));
}

// ---------------------------------------------------------------------------
// fused: w16[kk][o][ic] = fp16(cw[o][ic][kk]);  wsq[o,i] = sum_k cw^2
// grid(COUT*CIN/256), block(256)
// ---------------------------------------------------------------------------
__global__ void k_prep_w(const float* __restrict__ cw) {
    const int idx = blockIdx.x * blockDim.x + threadIdx.x;  // o*512+ic
    const float* __restrict__ p = cw + (long)idx * 9;
    float v[9];
    float s = 0.f;
#pragma unroll
    for (int k = 0; k < 9; k++) { v[k] = p[k]; s += v[k] * v[k]; }
    g_wsq[idx] = s;
#pragma unroll
    for (int kk = 0; kk < 9; kk++)
        g_w16[kk * (COUT * CIN) + idx] = __float2half(v[kk]);
}

// ---------------------------------------------------------------------------
// fused style + demod:
//   s[b,i] = style @ (aff_w/sqrt(512))^T + bias + 1
//   d[b,o] = rsqrt(w_scale^2 * sum_i s^2*wsq + 1e-8)
// grid(B), block(512)
// ---------------------------------------------------------------------------
__global__ void k_style_demod(const float* __restrict__ style,
                              const float* __restrict__ aff_w,
                              const float* __restrict__ aff_b) {
    __shared__ float st[SDIM];
    __shared__ float s2[CIN];
    const int b = blockIdx.x, i = threadIdx.x;
    st[i] = style[b * SDIM + i];
    __syncthreads();
    const float aff_scale = 0.04419417382415922f;  // 1/sqrt(512)
    const float* __restrict__ wrow = aff_w + (long)i * SDIM;
    float acc = 0.f;
#pragma unroll 8
    for (int j = 0; j < SDIM; j++) acc += wrow[j] * st[j];
    const float sv = acc * aff_scale + aff_b[i] + 1.0f;
    g_s[b * CIN + i] = sv;
    s2[i] = sv * sv;
    __syncthreads();
    const float* __restrict__ wr = g_wsq + (long)i * CIN;
    float dacc = 0.f;
#pragma unroll 8
    for (int j = 0; j < CIN; j++) dacc += wr[j] * s2[j];
    g_d[b * COUT + i] = rsqrtf(dacc * (1.0f / 4608.0f) + 1e-8f);
}

// ---------------------------------------------------------------------------
// x16[b][y+1][x+1][ic] = fp16(s[b,ic] * x[b,ic,y,x]); halo zeroed here too.
// grid(16 b, 16 ic-chunks), block(256)
// ---------------------------------------------------------------------------
__global__ void k_prep_x(const float* __restrict__ x) {
    __shared__ float t[32][133];           // [ic][r*33+xc]
    __shared__ float sm[32];
    const int b = blockIdx.x;
    const int ic0 = blockIdx.y * 32;
    const int tid = threadIdx.x;
    if (tid < 32) sm[tid] = g_s[b * CIN + ic0 + tid];

    // ---- zero halo for this block's 32 channels: 132 halo pixels ----
#pragma unroll
    for (int i = 0; i < 9; i++) {
        const int idx = i * 256 + tid;               // 2112 half2 writes
        if (idx < 2112) {
            const int pos  = idx >> 4;               // 0..131
            const int pair = idx & 15;
            int yy, xx;
            if (pos < 34)       { yy = 0;         xx = pos; }
            else if (pos < 68)  { yy = 33;        xx = pos - 34; }
            else if (pos < 100) { yy = pos - 67;  xx = 0; }
            else                { yy = pos - 99;  xx = 33; }
            *reinterpret_cast<__half2*>(
                g_x16 + (((long)b * 34 + yy) * 34 + xx) * CIN + ic0 + pair * 2) =
                __floats2half2_rn(0.f, 0.f);
        }
    }
    __syncthreads();

    for (int y0 = 0; y0 < 32; y0 += 4) {
#pragma unroll
        for (int i = 0; i < 16; i++) {
            const int idx = i * 256 + tid;          // 4096 elems
            const int ic = idx >> 7;
            const int p  = idx & 127;
            const int r  = p >> 5, xc = p & 31;
            t[ic][r * 33 + xc] =
                x[(((long)b * CIN + ic0 + ic) * 32 + y0 + r) * 32 + xc] * sm[ic];
        }
        __syncthreads();
#pragma unroll
        for (int i = 0; i < 8; i++) {
            const int idx = i * 256 + tid;          // 2048 half2
            const int p    = idx >> 4;
            const int pair = idx & 15;
            const int r = p >> 5, xc = p & 31;
            const int ic = pair * 2;
            __half2 h = __floats2half2_rn(t[ic][r * 33 + xc], t[ic + 1][r * 33 + xc]);
            *reinterpret_cast<__half2*>(
                g_x16 + (((long)b * 34 + y0 + r + 1) * 34 + xc + 1) * CIN + ic0 + ic) = h;
        }
        __syncthreads();
    }
}

// ---------------------------------------------------------------------------
// Implicit-GEMM conv via warp MMA (HMMA m16n8k16, fp16 in / fp32 acc).
// CTA: [M=128 out-ch, N=128 px (4 rows)]. 8 warps (2M x 4N), warp tile 64x32.
// K: 72 chunks of 64 (9 taps x 8 ic-chunks).
// 3-stage cp.async ring, wait_group(1): group c has a 2-iteration DMA window.
// One commit per iteration (empty groups keep the drain count aligned).
// grid(4, 8, 16), block(256), dyn smem 3 x 36,864 B = 110,592 B
// ---------------------------------------------------------------------------
#define ASTRIDE 144       // 128B data + 16B pad (conflict-free LDSM: 4-bank shift)
#define ABUF    18432     // 128 rows * 144B
#define STAGESZ 36864     // A + B per stage
#define NSTAGE  3
#define NCHUNK  72

extern __shared__ unsigned char sbuf_dyn[];

__global__ void __launch_bounds__(256, 2)
k_conv_mma(float* __restrict__ out) {
    const int b  = blockIdx.z;
    const int o0 = blockIdx.x * 128;
    const int y0 = blockIdx.y * 4;
    const int tid  = threadIdx.x;
    const int lane = tid & 31;
    const int wid  = tid >> 5;
    const int wm   = wid >> 2;     // 0..1  (M)
    const int wn   = wid & 3;      // 0..3  (N: one output row each)

    const uint32_t sb = smem_u32(sbuf_dyn);

    // loader coords: seg = 16B segment of a 128B row; r = base row (0..31)
    const int seg = tid & 7;
    const int r   = tid >> 3;

    float acc[4][4][4];
#pragma unroll
    for (int i = 0; i < 4; i++)
#pragma unroll
        for (int j = 0; j < 4; j++)
#pragma unroll
            for (int k = 0; k < 4; k++) acc[i][j][k] = 0.f;

    auto prefetch = [&](int c, int st) {
        const int kk  = c >> 3;              // tap 0..8
        const int ic0 = (c & 7) << 6;        // 0,64,...,448
        const int ky  = kk / 3;
        const int kx  = kk - ky * 3;
        const uint32_t sa = sb + st * STAGESZ;
        const uint32_t sB = sa + ABUF;
        const __half* __restrict__ wa =
            g_w16 + (long)kk * (COUT * CIN) + ic0 + seg * 8;
        const __half* __restrict__ xb =
            g_x16 + (((long)b * 34 + y0 + ky) * 34 + (r + kx)) * CIN + ic0 + seg * 8;
#pragma unroll
        for (int k4 = 0; k4 < 4; k4++) {
            const int row = r + k4 * 32;     // A row = out-ch; B row = pixel
            cp16(sa + row * ASTRIDE + seg * 16, wa + (long)(o0 + row) * CIN);
            cp16(sB + row * ASTRIDE + seg * 16, xb + (long)k4 * 34 * CIN);
        }
    };

    prefetch(0, 0);
    CP_COMMIT();
    prefetch(1, 1);
    CP_COMMIT();

    int st = 0;
    for (int c = 0; c < NCHUNK; c++) {
        CP_WAIT1();                      // group c complete (c+1 may be in flight)
        __syncthreads();                 // publish all threads' copies; close compute(c-1)
        if (c + 2 < NCHUNK) {
            // stage (c+2)%3 == stage (c-1)%3: last read in compute(c-1), closed by sync
            const int st2 = (st + 2 < NSTAGE) ? st + 2 : st + 2 - NSTAGE;
            prefetch(c + 2, st2);
        }
        CP_COMMIT();                     // always commit (empty groups keep count aligned)

        const uint32_t A = sb + st * STAGESZ;
        const uint32_t B = A + ABUF;
#pragma unroll
        for (int kh = 0; kh < 4; kh++) {
            uint32_t af[4][4], bf[2][4];
#pragma unroll
            for (int mt = 0; mt < 4; mt++) {
                const uint32_t row = wm * 64 + mt * 16 + (lane & 15);
                ldsm_x4(af[mt], A + row * ASTRIDE + kh * 32 + (lane >> 4) * 16);
            }
#pragma unroll
            for (int g = 0; g < 2; g++) {
                const uint32_t n = wn * 32 + g * 16 + ((lane >> 4) << 3) + (lane & 7);
                ldsm_x4(bf[g], B + n * ASTRIDE + kh * 32 + ((lane >> 3) & 1) * 16);
            }
#pragma unroll
            for (int mt = 0; mt < 4; mt++)
#pragma unroll
                for (int nt = 0; nt < 4; nt++)
                    mma16816(acc[mt][nt], af[mt], bf[nt >> 1] + (nt & 1) * 2);
        }
        st = (st + 1 < NSTAGE) ? st + 1 : 0;
    }

    // ---- epilogue: demod scale, direct coalesced v2 stores ----
    const float wsc = 0.014731391274719736f;  // 1/sqrt(4608)
    const int y = y0 + wn;                     // this warp's output row
#pragma unroll
    for (int mt = 0; mt < 4; mt++) {
        const int rr   = wm * 64 + mt * 16 + (lane >> 2);
        const int o_lo = o0 + rr;
        const int o_hi = o_lo + 8;
        const float d0 = g_d[b * COUT + o_lo] * wsc;
        const float d1 = g_d[b * COUT + o_hi] * wsc;
#pragma unroll
        for (int nt = 0; nt < 4; nt++) {
            const int xcol = nt * 8 + (lane & 3) * 2;
            float2 v0 = make_float2(acc[mt][nt][0] * d0, acc[mt][nt][1] * d0);
            float2 v1 = make_float2(acc[mt][nt][2] * d1, acc[mt][nt][3] * d1);
            *reinterpret_cast<float2*>(
                &out[(((long)b * COUT + o_lo) * 32 + y) * 32 + xcol]) = v0;
            *reinterpret_cast<float2*>(
                &out[(((long)b * COUT + o_hi) * 32 + y) * 32 + xcol]) = v1;
        }
    }
}

// ---------------------------------------------------------------------------
extern "C" void kernel_launch(void* const* d_in, const int* in_sizes, int n_in,
                              void* d_out, int out_size) {
    const float* x      = (const float*)d_in[0];  // [16,512,32,32]
    const float* style  = (const float*)d_in[1];  // [16,512]
    const float* aff_w  = (const float*)d_in[2];  // [512,512]
    const float* aff_b  = (const float*)d_in[3];  // [512]
    const float* cw     = (const float*)d_in[4];  // [512,512,3,3]
    float* out          = (float*)d_out;          // [16,512,32,32]

    // unconditional + idempotent (no static guards allowed)
    cudaFuncSetAttribute(k_conv_mma,
                         cudaFuncAttributeMaxDynamicSharedMemorySize,
                         NSTAGE * STAGESZ);

    k_prep_w<<<(COUT * CIN) / 256, 256>>>(cw);
    k_style_demod<<<Bsz, SDIM>>>(style, aff_w, aff_b);
    k_prep_x<<<dim3(Bsz, CIN / 32), 256>>>(x);
    k_conv_mma<<<dim3(COUT / 128, 8, Bsz), 256, NSTAGE * STAGESZ>>>(out);
}

// round 7
// speedup vs baseline: 8.9087x; 1.7369x over previous
#include <cuda_runtime.h>
#include <cuda_fp16.h>
#include <cstdint>

#define Bsz   16
#define CIN   512
#define COUT  512
#define SDIM  512
#define HWDIM 32

// ---------------- scratch (__device__ globals; no allocations) --------------
__device__ float g_s[Bsz * CIN];            // modulation s[b,i]
__device__ float g_d[Bsz * COUT];           // demod d[b,o]
__device__ float g_wsq[COUT * CIN];         // sum_k cw^2
__device__ __align__(16) __half g_w16[9 * COUT * CIN];          // [kk][o][ic]
__device__ __align__(16) __half g_x16[Bsz * 34 * 34 * CIN];     // [b][yy][xx][ic], zero halo

// ---------------- PTX helpers (base ISA only) --------------------------------
__device__ __forceinline__ uint32_t smem_u32(const void* p) {
    uint32_t a;
    asm("{ .reg .u64 t; cvta.to.shared.u64 t, %1; cvt.u32.u64 %0, t; }"
        : "=r"(a) : "l"(p));
    return a;
}
__device__ __forceinline__ void cp16(uint32_t s, const void* g) {
    asm volatile("cp.async.cg.shared.global [%0], [%1], 16;" :: "r"(s), "l"(g));
}
#define CP_COMMIT() asm volatile("cp.async.commit_group;" ::: "memory")
#define CP_WAIT0()  asm volatile("cp.async.wait_group 0;" ::: "memory")

__device__ __forceinline__ void ldsm_x4(uint32_t* r, uint32_t addr) {
    asm volatile("ldmatrix.sync.aligned.m8n8.x4.shared.b16 {%0,%1,%2,%3}, [%4];"
        : "=r"(r[0]), "=r"(r[1]), "=r"(r[2]), "=r"(r[3]) : "r"(addr));
}
__device__ __forceinline__ void mma16816(float* c, const uint32_t* a, const uint32_t* b) {
    asm volatile("mma.sync.aligned.m16n8k16.row.col.f32.f16.f16.f32 "
        "{%0,%1,%2,%3}, {%4,%5,%6,%7}, {%8,%9}, {%0,%1,%2,%3};"
        : "+f"(c[0]), "+f"(c[1]), "+f"(c[2]), "+f"(c[3])
        : "r"(a[0]), "r"(a[1]), "r"(a[2]), "r"(a[3]), "r"(b[0]), "r"(b[1]));
}

// ---------------------------------------------------------------------------
// fused: w16[kk][o][ic] = fp16(cw[o][ic][kk]);  wsq[o,i] = sum_k cw^2
// grid(COUT*CIN/256), block(256)
// ---------------------------------------------------------------------------
__global__ void k_prep_w(const float* __restrict__ cw) {
    const int idx = blockIdx.x * blockDim.x + threadIdx.x;  // o*512+ic
    const float* __restrict__ p = cw + (long)idx * 9;
    float v[9];
    float s = 0.f;
#pragma unroll
    for (int k = 0; k < 9; k++) { v[k] = p[k]; s += v[k] * v[k]; }
    g_wsq[idx] = s;
#pragma unroll
    for (int kk = 0; kk < 9; kk++)
        g_w16[kk * (COUT * CIN) + idx] = __float2half(v[kk]);
}

// ---------------------------------------------------------------------------
// s[b,i] = style @ (aff_w/sqrt(512))^T + bias + 1     grid(16,4), block(128)
// ---------------------------------------------------------------------------
__global__ void k_style(const float* __restrict__ style,
                        const float* __restrict__ aff_w,
                        const float* __restrict__ aff_b) {
    __shared__ float st[SDIM];
    const int b = blockIdx.x;
    const int tid = threadIdx.x;
    for (int j = tid; j < SDIM; j += 128) st[j] = style[b * SDIM + j];
    __syncthreads();
    const int i = blockIdx.y * 128 + tid;
    const float aff_scale = 0.04419417382415922f;  // 1/sqrt(512)
    const float* __restrict__ wrow = aff_w + (long)i * SDIM;
    float acc = 0.f;
#pragma unroll 8
    for (int j = 0; j < SDIM; j++) acc += wrow[j] * st[j];
    g_s[b * CIN + i] = acc * aff_scale + aff_b[i] + 1.0f;
}

// ---------------------------------------------------------------------------
// d[b,o] = rsqrt(w_scale^2 * sum_i s^2*wsq + 1e-8)    grid(16,4), block(128)
// ---------------------------------------------------------------------------
__global__ void k_demod() {
    __shared__ float s2[CIN];
    const int b = blockIdx.x;
    const int tid = threadIdx.x;
    for (int j = tid; j < CIN; j += 128) {
        const float v = g_s[b * CIN + j];
        s2[j] = v * v;
    }
    __syncthreads();
    const int o = blockIdx.y * 128 + tid;
    const float* __restrict__ wr = g_wsq + (long)o * CIN;
    float acc = 0.f;
#pragma unroll 8
    for (int j = 0; j < CIN; j++) acc += wr[j] * s2[j];
    g_d[b * COUT + o] = rsqrtf(acc * (1.0f / 4608.0f) + 1e-8f);
}

// ---------------------------------------------------------------------------
// x16[b][y+1][x+1][ic] = fp16(s[b,ic] * x[b,ic,y,x]); halo zeroed by yq==0.
// grid(16 b, 16 ic-chunks, 4 y-quadrants), block(256)
// ---------------------------------------------------------------------------
__global__ void k_prep_x(const float* __restrict__ x) {
    __shared__ float t[32][133];           // [ic][r*33+xc]
    __shared__ float sm[32];
    const int b   = blockIdx.x;
    const int ic0 = blockIdx.y * 32;
    const int yq  = blockIdx.z;
    const int tid = threadIdx.x;
    if (tid < 32) sm[tid] = g_s[b * CIN + ic0 + tid];

    if (yq == 0) {
        // ---- zero halo for this block's 32 channels: 132 halo pixels ----
#pragma unroll
        for (int i = 0; i < 9; i++) {
            const int idx = i * 256 + tid;               // 2112 half2 writes
            if (idx < 2112) {
                const int pos  = idx >> 4;               // 0..131
                const int pair = idx & 15;
                int yy, xx;
                if (pos < 34)       { yy = 0;         xx = pos; }
                else if (pos < 68)  { yy = 33;        xx = pos - 34; }
                else if (pos < 100) { yy = pos - 67;  xx = 0; }
                else                { yy = pos - 99;  xx = 33; }
                *reinterpret_cast<__half2*>(
                    g_x16 + (((long)b * 34 + yy) * 34 + xx) * CIN + ic0 + pair * 2) =
                    __floats2half2_rn(0.f, 0.f);
            }
        }
    }
    __syncthreads();

    for (int y0 = yq * 8; y0 < yq * 8 + 8; y0 += 4) {
#pragma unroll
        for (int i = 0; i < 16; i++) {
            const int idx = i * 256 + tid;          // 4096 elems
            const int ic = idx >> 7;
            const int p  = idx & 127;
            const int r  = p >> 5, xc = p & 31;
            t[ic][r * 33 + xc] =
                x[(((long)b * CIN + ic0 + ic) * 32 + y0 + r) * 32 + xc] * sm[ic];
        }
        __syncthreads();
#pragma unroll
        for (int i = 0; i < 8; i++) {
            const int idx = i * 256 + tid;          // 2048 half2
            const int p    = idx >> 4;
            const int pair = idx & 15;
            const int r = p >> 5, xc = p & 31;
            const int ic = pair * 2;
            __half2 h = __floats2half2_rn(t[ic][r * 33 + xc], t[ic + 1][r * 33 + xc]);
            *reinterpret_cast<__half2*>(
                g_x16 + (((long)b * 34 + y0 + r + 1) * 34 + xc + 1) * CIN + ic0 + ic) = h;
        }
        __syncthreads();
    }
}

// ---------------------------------------------------------------------------
// Implicit-GEMM conv via warp MMA (HMMA m16n8k16, fp16 in / fp32 acc).
// CTA: [M=128 out-ch, N=64 px (2 rows)]. 4 warps (2M x 2N), warp tile 64x32.
// K: 72 chunks of 64. 2-stage cp.async, 1 sync/chunk.
// 4 CTAs/SM: finer barriers, interleaved pipelines across CTAs.
// grid(4, 16, 16), block(128), dyn smem 2 x 27,648 B
// ---------------------------------------------------------------------------
#define ASTRIDE 144       // 128B data + 16B pad (conflict-free LDSM)
#define ABUF    18432     // 128 rows * 144B
#define BBUF    9216      // 64 rows * 144B
#define STAGESZ 27648     // A + B per stage
#define NCHUNK  72

extern __shared__ unsigned char sbuf_dyn[];

__global__ void __launch_bounds__(128, 4)
k_conv_mma(float* __restrict__ out) {
    const int b  = blockIdx.z;
    const int o0 = blockIdx.x * 128;
    const int y0 = blockIdx.y * 2;
    const int tid  = threadIdx.x;
    const int lane = tid & 31;
    const int wid  = tid >> 5;
    const int wm   = wid >> 1;     // 0..1  (M)
    const int wn   = wid & 1;      // 0..1  (N: one output row each)

    const uint32_t sb = smem_u32(sbuf_dyn);

    // loader coords: seg = 16B segment of a 128B row; r = base row (0..15)
    const int seg = tid & 7;
    const int r   = tid >> 3;

    float acc[4][4][4];
#pragma unroll
    for (int i = 0; i < 4; i++)
#pragma unroll
        for (int j = 0; j < 4; j++)
#pragma unroll
            for (int k = 0; k < 4; k++) acc[i][j][k] = 0.f;

    auto prefetch = [&](int c, int bi) {
        const int kk  = c >> 3;              // tap 0..8
        const int ic0 = (c & 7) << 6;        // 0,64,...,448
        const int ky  = kk / 3;
        const int kx  = kk - ky * 3;
        const uint32_t sa = sb + bi * STAGESZ;
        const uint32_t sB = sa + ABUF;
        const __half* __restrict__ wa =
            g_w16 + (long)kk * (COUT * CIN) + ic0 + seg * 8;
#pragma unroll
        for (int k8 = 0; k8 < 8; k8++) {
            const int row = r + k8 * 16;     // A row = out-ch
            cp16(sa + row * ASTRIDE + seg * 16, wa + (long)(o0 + row) * CIN);
        }
#pragma unroll
        for (int k4 = 0; k4 < 4; k4++) {
            const int p  = r + k4 * 16;      // B row = pixel 0..63
            const int yy = y0 + (p >> 5) + ky;
            const int xx = (p & 31) + kx;
            cp16(sB + p * ASTRIDE + seg * 16,
                 g_x16 + (((long)b * 34 + yy) * 34 + xx) * CIN + ic0 + seg * 8);
        }
    };

    prefetch(0, 0);
    CP_COMMIT();

    for (int c = 0; c < NCHUNK; c++) {
        const int bi = c & 1;
        CP_WAIT0();                      // my copies of group c done
        __syncthreads();                 // publish all threads' copies; close compute(c-1)
        if (c + 1 < NCHUNK) {
            prefetch(c + 1, bi ^ 1);     // safe: bi^1 last read in compute(c-1)
            CP_COMMIT();
        }

        const uint32_t A = sb + bi * STAGESZ;
        const uint32_t B = A + ABUF;
#pragma unroll
        for (int kh = 0; kh < 4; kh++) {
            uint32_t af[4][4], bf[2][4];
#pragma unroll
            for (int mt = 0; mt < 4; mt++) {
                const uint32_t row = wm * 64 + mt * 16 + (lane & 15);
                ldsm_x4(af[mt], A + row * ASTRIDE + kh * 32 + (lane >> 4) * 16);
            }
#pragma unroll
            for (int g = 0; g < 2; g++) {
                const uint32_t n = wn * 32 + g * 16 + ((lane >> 4) << 3) + (lane & 7);
                ldsm_x4(bf[g], B + n * ASTRIDE + kh * 32 + ((lane >> 3) & 1) * 16);
            }
#pragma unroll
            for (int mt = 0; mt < 4; mt++)
#pragma unroll
                for (int nt = 0; nt < 4; nt++)
                    mma16816(acc[mt][nt], af[mt], bf[nt >> 1] + (nt & 1) * 2);
        }
    }

    // ---- epilogue: demod scale, direct coalesced v2 stores ----
    const float wsc = 0.014731391274719736f;  // 1/sqrt(4608)
    const int y = y0 + wn;                     // this warp's output row
#pragma unroll
    for (int mt = 0; mt < 4; mt++) {
        const int rr   = wm * 64 + mt * 16 + (lane >> 2);
        const int o_lo = o0 + rr;
        const int o_hi = o_lo + 8;
        const float d0 = g_d[b * COUT + o_lo] * wsc;
        const float d1 = g_d[b * COUT + o_hi] * wsc;
#pragma unroll
        for (int nt = 0; nt < 4; nt++) {
            const int xcol = nt * 8 + (lane & 3) * 2;
            float2 v0 = make_float2(acc[mt][nt][0] * d0, acc[mt][nt][1] * d0);
            float2 v1 = make_float2(acc[mt][nt][2] * d1, acc[mt][nt][3] * d1);
            *reinterpret_cast<float2*>(
                &out[(((long)b * COUT + o_lo) * 32 + y) * 32 + xcol]) = v0;
            *reinterpret_cast<float2*>(
                &out[(((long)b * COUT + o_hi) * 32 + y) * 32 + xcol]) = v1;
        }
    }
}

// ---------------------------------------------------------------------------
extern "C" void kernel_launch(void* const* d_in, const int* in_sizes, int n_in,
                              void* d_out, int out_size) {
    const float* x      = (const float*)d_in[0];  // [16,512,32,32]
    const float* style  = (const float*)d_in[1];  // [16,512]
    const float* aff_w  = (const float*)d_in[2];  // [512,512]
    const float* aff_b  = (const float*)d_in[3];  // [512]
    const float* cw     = (const float*)d_in[4];  // [512,512,3,3]
    float* out          = (float*)d_out;          // [16,512,32,32]

    // unconditional + idempotent (no static guards allowed)
    cudaFuncSetAttribute(k_conv_mma,
                         cudaFuncAttributeMaxDynamicSharedMemorySize,
                         2 * STAGESZ);

    k_prep_w<<<(COUT * CIN) / 256, 256>>>(cw);
    k_style<<<dim3(Bsz, 4), 128>>>(style, aff_w, aff_b);
    k_demod<<<dim3(Bsz, 4), 128>>>();
    k_prep_x<<<dim3(Bsz, CIN / 32, 4), 256>>>(x);
    k_conv_mma<<<dim3(COUT / 128, 16, Bsz), 128, 2 * STAGESZ>>>(out);
}